// round 7
// baseline (speedup 1.0000x reference)
#include <cuda_runtime.h>
#include <cstdint>

#define N_NODES 100000
#define N_EDGES 1600000

typedef unsigned long long u64;

// ---------------- device scratch (static: no allocations allowed) -------------
__device__ float g_agg[(size_t)N_NODES * 256];
__device__ float g_h1 [(size_t)N_NODES * 256];
__device__ float g_h2 [(size_t)N_NODES * 256];
__device__ float g_deginv[N_NODES];
__device__ int   g_deg[N_NODES];
__device__ int   g_rowptr[N_NODES + 1];
__device__ int   g_cursor[N_NODES];
__device__ int   g_csr[N_EDGES];
__device__ int   g_is64;
__device__ float g_s1[256], g_t1[256], g_s2[256], g_t2[256], g_s3[64], g_t3[64];

// ---------------- packed f32x2 helpers ---------------------------------------
__device__ __forceinline__ u64 pack2(float lo, float hi) {
    u64 r; asm("mov.b64 %0, {%1, %2};" : "=l"(r) : "f"(lo), "f"(hi)); return r;
}
__device__ __forceinline__ void unpack2(u64 v, float& lo, float& hi) {
    asm("mov.b64 {%0, %1}, %2;" : "=f"(lo), "=f"(hi) : "l"(v));
}
__device__ __forceinline__ void ffma2(u64& d, u64 a, u64 b) {
    asm("fma.rn.f32x2 %0, %1, %2, %0;" : "+l"(d) : "l"(a), "l"(b));
}

// ---------------- index dtype detection (int32 vs int64 edge_index) ----------
__global__ void detect_kernel(const void* ei) {
    const unsigned long long* p = (const unsigned long long*)ei;
    int is64 = 1;
    for (int i = 0; i < 64; i++)
        if (p[i] >= (unsigned long long)N_NODES) { is64 = 0; break; }
    g_is64 = is64;
}

__device__ __forceinline__ int load_idx(const void* p, long long i, int is64) {
    if (is64) return (int)((const long long*)p)[i];
    return ((const int*)p)[i];
}

// ---------------- prep: fold bias+BN into per-channel scale/shift ------------
__global__ void prep_kernel(const float* b1, const float* g1, const float* be1,
                            const float* rm1, const float* rv1,
                            const float* b2, const float* g2, const float* be2,
                            const float* rm2, const float* rv2,
                            const float* bcl) {
    int j = threadIdx.x;
    if (j < 256) {
        float s = g1[j] * rsqrtf(rv1[j] + 1e-5f);
        g_s1[j] = s; g_t1[j] = be1[j] + (b1[j] - rm1[j]) * s;
        s = g2[j] * rsqrtf(rv2[j] + 1e-5f);
        g_s2[j] = s; g_t2[j] = be2[j] + (b2[j] - rm2[j]) * s;
    }
    if (j < 64) { g_s3[j] = 1.0f; g_t3[j] = bcl[j]; }
}

// ---------------- CSR build --------------------------------------------------
__global__ void deg_count_kernel(const void* ei) {
    int e = blockIdx.x * blockDim.x + threadIdx.x;
    if (e < N_EDGES) {
        int d = load_idx(ei, (long long)N_EDGES + e, g_is64);
        atomicAdd(&g_deg[d], 1);
    }
}

__global__ void deginv_kernel() {
    int n = blockIdx.x * blockDim.x + threadIdx.x;
    if (n < N_NODES) {
        int d = g_deg[n];
        g_deginv[n] = (d > 0) ? (1.0f / (float)d) : 0.0f;
    }
}

// exclusive scan of g_deg -> g_rowptr, single block of 1024, chunked
__global__ void scan_kernel() {
    __shared__ int sh[1024];
    int tid = threadIdx.x;
    int carry = 0;
    for (int base = 0; base < N_NODES; base += 1024) {
        int idx = base + tid;
        int v = (idx < N_NODES) ? g_deg[idx] : 0;
        sh[tid] = v;
        __syncthreads();
        #pragma unroll
        for (int off = 1; off < 1024; off <<= 1) {
            int t = (tid >= off) ? sh[tid - off] : 0;
            __syncthreads();
            sh[tid] += t;
            __syncthreads();
        }
        if (idx < N_NODES) g_rowptr[idx] = carry + sh[tid] - v;
        carry += sh[1023];
        __syncthreads();
    }
    if (tid == 0) g_rowptr[N_NODES] = carry;
}

__global__ void csr_fill_kernel(const void* ei) {
    int e = blockIdx.x * blockDim.x + threadIdx.x;
    if (e < N_EDGES) {
        int is64 = g_is64;
        int s = load_idx(ei, e, is64);
        int d = load_idx(ei, (long long)N_EDGES + e, is64);
        int pos = atomicAdd(&g_cursor[d], 1);
        g_csr[g_rowptr[d] + pos] = s;
    }
}

// ---------------- mean aggregation (gather over CSR) -------------------------
// one block per node; thread t owns channels [4t, 4t+4)
template <int C>
__global__ void agg_mean_kernel(const float4* __restrict__ feat,
                                float4* __restrict__ out) {
    constexpr int CV = C / 4;
    int n  = blockIdx.x;
    int ch = threadIdx.x;
    int beg = g_rowptr[n], end = g_rowptr[n + 1];
    float4 s0 = make_float4(0.f, 0.f, 0.f, 0.f);
    float4 s1 = make_float4(0.f, 0.f, 0.f, 0.f);
    int i = beg;
    for (; i + 2 <= end; i += 2) {
        int na = g_csr[i], nb = g_csr[i + 1];
        float4 va = feat[(size_t)na * CV + ch];
        float4 vb = feat[(size_t)nb * CV + ch];
        s0.x += va.x; s0.y += va.y; s0.z += va.z; s0.w += va.w;
        s1.x += vb.x; s1.y += vb.y; s1.z += vb.z; s1.w += vb.w;
    }
    if (i < end) {
        int na = g_csr[i];
        float4 va = feat[(size_t)na * CV + ch];
        s0.x += va.x; s0.y += va.y; s0.z += va.z; s0.w += va.w;
    }
    float d = g_deginv[n];
    float4 r;
    r.x = (s0.x + s1.x) * d; r.y = (s0.y + s1.y) * d;
    r.z = (s0.z + s1.z) * d; r.w = (s0.w + s1.w) * d;
    out[(size_t)n * CV + ch] = r;
}

// ---------------- fused dual-GEMM: out = relu_bn( A0@B0 + A1@B1 ) -----------
// A0:[N,K1] (mean), A1:[N,K2] (self), B0:[K1,COUT], B1:[K2,COUT]
// mainloop uses packed fma.rn.f32x2: A M-pairs come packed straight from smem
// (adjacent M contiguous in As), B values lane-duplicated via one mov.b64.
// epilogue: v = acc*scale[col] + shift[col]; optional relu
template <int K1, int K2, int COUT, int BN, int TN, bool RELU>
__global__ __launch_bounds__(256, 2)
void gemm_fused_kernel(const float* __restrict__ A0, const float* __restrict__ A1,
                       const float* __restrict__ B0, const float* __restrict__ B1,
                       const float* __restrict__ scale, const float* __restrict__ shift,
                       float* __restrict__ out, int Nrows) {
    constexpr int BM = 128, BK = 8, TM = 8;
    __shared__ float As[BK][BM + 4];   // row stride 132 floats = 528 B (16B aligned)
    __shared__ float Bs[BK][BN];

    int tid = threadIdx.x;
    int tx = tid & 15, ty = tid >> 4;
    int row0 = blockIdx.x * BM;
    int jb = blockIdx.y * BN;

    // packed accumulators: acc2[i2][j] lanes = rows (2*i2, 2*i2+1), col j
    u64 acc2[TM / 2][TN];
    #pragma unroll
    for (int i = 0; i < TM / 2; i++)
        #pragma unroll
        for (int j = 0; j < TN; j++) acc2[i][j] = 0ull;

    // A tile loader: tid -> (row 0..127, 4-col segment 0..1)
    int rowA = tid >> 1;
    int cseg = tid & 1;
    int mA = row0 + rowA; if (mA >= Nrows) mA = Nrows - 1;

    // B tile loader mapping
    int rowB, cB; bool bload;
    if (BN == 128) { rowB = tid >> 5; cB = (tid & 31) * 4; bload = true; }
    else           { rowB = tid >> 4; cB = (tid & 15) * 4; bload = (tid < 128); }

    constexpr int KT = (K1 + K2) / BK;
    #pragma unroll 1
    for (int kk = 0; kk < KT; kk++) {
        int kbase = kk * BK;
        const float* Ap;
        const float* Bp;
        if (kbase < K1) {
            Ap = A0 + (size_t)mA * K1 + kbase;
            Bp = B0 + (size_t)kbase * COUT;
        } else {
            Ap = A1 + (size_t)mA * K2 + (kbase - K1);
            Bp = B1 + (size_t)(kbase - K1) * COUT;
        }
        float4 av = *reinterpret_cast<const float4*>(Ap + cseg * 4);
        float4 bv = make_float4(0.f, 0.f, 0.f, 0.f);
        if (bload) bv = *reinterpret_cast<const float4*>(Bp + (size_t)rowB * COUT + jb + cB);

        __syncthreads();
        As[cseg * 4 + 0][rowA] = av.x;
        As[cseg * 4 + 1][rowA] = av.y;
        As[cseg * 4 + 2][rowA] = av.z;
        As[cseg * 4 + 3][rowA] = av.w;
        if (bload) *reinterpret_cast<float4*>(&Bs[rowB][cB]) = bv;
        __syncthreads();

        #pragma unroll
        for (int k = 0; k < BK; k++) {
            // A: 8 rows = 4 packed M-pairs, loaded pre-packed from smem
            ulonglong2 aA = *reinterpret_cast<const ulonglong2*>(&As[k][ty * TM]);
            ulonglong2 aB = *reinterpret_cast<const ulonglong2*>(&As[k][ty * TM + 4]);
            u64 ap[TM / 2];
            ap[0] = aA.x; ap[1] = aA.y; ap[2] = aB.x; ap[3] = aB.y;

            float bb[TN];
            float4 b0 = *reinterpret_cast<const float4*>(&Bs[k][tx * TN]);
            bb[0] = b0.x; bb[1] = b0.y; bb[2] = b0.z; bb[3] = b0.w;
            if (TN == 8) {
                float4 b1v = *reinterpret_cast<const float4*>(&Bs[k][tx * TN + 4]);
                bb[4] = b1v.x; bb[5] = b1v.y; bb[6] = b1v.z; bb[7] = b1v.w;
            }
            u64 bp[TN];
            #pragma unroll
            for (int j = 0; j < TN; j++) bp[j] = pack2(bb[j], bb[j]);

            #pragma unroll
            for (int i = 0; i < TM / 2; i++)
                #pragma unroll
                for (int j = 0; j < TN; j++)
                    ffma2(acc2[i][j], ap[i], bp[j]);
        }
    }

    // unpack packed accumulators into per-row scalars
    float accf[TM][TN];
    #pragma unroll
    for (int i = 0; i < TM / 2; i++)
        #pragma unroll
        for (int j = 0; j < TN; j++)
            unpack2(acc2[i][j], accf[2 * i][j], accf[2 * i + 1][j]);

    // epilogue: per-channel affine (+relu), vectorized stores
    float sc[TN], sf[TN];
    #pragma unroll
    for (int j = 0; j < TN; j++) {
        int col = jb + tx * TN + j;
        sc[j] = scale[col];
        sf[j] = shift[col];
    }
    #pragma unroll
    for (int i = 0; i < TM; i++) {
        int m = row0 + ty * TM + i;
        if (m < Nrows) {
            #pragma unroll
            for (int g = 0; g < TN / 4; g++) {
                float4 v;
                v.x = accf[i][g*4+0] * sc[g*4+0] + sf[g*4+0];
                v.y = accf[i][g*4+1] * sc[g*4+1] + sf[g*4+1];
                v.z = accf[i][g*4+2] * sc[g*4+2] + sf[g*4+2];
                v.w = accf[i][g*4+3] * sc[g*4+3] + sf[g*4+3];
                if (RELU) {
                    v.x = fmaxf(v.x, 0.f); v.y = fmaxf(v.y, 0.f);
                    v.z = fmaxf(v.z, 0.f); v.w = fmaxf(v.w, 0.f);
                }
                int col = jb + tx * TN + g * 4;
                *reinterpret_cast<float4*>(&out[(size_t)m * COUT + col]) = v;
            }
        }
    }
}

// ---------------- launch -----------------------------------------------------
extern "C" void kernel_launch(void* const* d_in, const int* in_sizes, int n_in,
                              void* d_out, int out_size) {
    const float* x   = (const float*)d_in[0];
    const void*  ei  = d_in[1];
    const float* W1l = (const float*)d_in[2];
    const float* b1l = (const float*)d_in[3];
    const float* W1r = (const float*)d_in[4];
    const float* g1  = (const float*)d_in[5];
    const float* be1 = (const float*)d_in[6];
    const float* rm1 = (const float*)d_in[7];
    const float* rv1 = (const float*)d_in[8];
    const float* W2l = (const float*)d_in[9];
    const float* b2l = (const float*)d_in[10];
    const float* W2r = (const float*)d_in[11];
    const float* g2  = (const float*)d_in[12];
    const float* be2 = (const float*)d_in[13];
    const float* rm2 = (const float*)d_in[14];
    const float* rv2 = (const float*)d_in[15];
    const float* Wcl = (const float*)d_in[16];
    const float* bcl = (const float*)d_in[17];
    const float* Wcr = (const float*)d_in[18];
    float* out = (float*)d_out;

    void *p_deg, *p_cursor, *p_agg, *p_h1, *p_h2, *p_s1, *p_t1, *p_s2, *p_t2, *p_s3, *p_t3;
    cudaGetSymbolAddress(&p_deg,    g_deg);
    cudaGetSymbolAddress(&p_cursor, g_cursor);
    cudaGetSymbolAddress(&p_agg,    g_agg);
    cudaGetSymbolAddress(&p_h1,     g_h1);
    cudaGetSymbolAddress(&p_h2,     g_h2);
    cudaGetSymbolAddress(&p_s1, g_s1); cudaGetSymbolAddress(&p_t1, g_t1);
    cudaGetSymbolAddress(&p_s2, g_s2); cudaGetSymbolAddress(&p_t2, g_t2);
    cudaGetSymbolAddress(&p_s3, g_s3); cudaGetSymbolAddress(&p_t3, g_t3);

    float* agg = (float*)p_agg;
    float* h1  = (float*)p_h1;
    float* h2  = (float*)p_h2;

    cudaMemsetAsync(p_deg,    0, N_NODES * sizeof(int), 0);
    cudaMemsetAsync(p_cursor, 0, N_NODES * sizeof(int), 0);

    detect_kernel<<<1, 1>>>(ei);
    prep_kernel<<<1, 256>>>(b1l, g1, be1, rm1, rv1, b2l, g2, be2, rm2, rv2, bcl);

    int eb = (N_EDGES + 255) / 256;
    deg_count_kernel<<<eb, 256>>>(ei);
    scan_kernel<<<1, 1024>>>();
    deginv_kernel<<<(N_NODES + 255) / 256, 256>>>();
    csr_fill_kernel<<<eb, 256>>>(ei);

    int gx = (N_NODES + 127) / 128;

    // layer 1: mean(x) -> agg [N,128]; h1 = relu(bn(agg@W1l + x@W1r + b1l))
    agg_mean_kernel<128><<<N_NODES, 32>>>((const float4*)x, (float4*)agg);
    gemm_fused_kernel<128, 128, 256, 128, 8, true>
        <<<dim3(gx, 2), 256>>>(agg, x, W1l, W1r, (const float*)p_s1, (const float*)p_t1, h1, N_NODES);

    // layer 2
    agg_mean_kernel<256><<<N_NODES, 64>>>((const float4*)h1, (float4*)agg);
    gemm_fused_kernel<256, 256, 256, 128, 8, true>
        <<<dim3(gx, 2), 256>>>(agg, h1, W2l, W2r, (const float*)p_s2, (const float*)p_t2, h2, N_NODES);

    // classifier
    agg_mean_kernel<256><<<N_NODES, 64>>>((const float4*)h2, (float4*)agg);
    gemm_fused_kernel<256, 256, 64, 64, 4, false>
        <<<dim3(gx, 1), 256>>>(agg, h2, Wcl, Wcr, (const float*)p_s3, (const float*)p_t3, out, N_NODES);
}

// round 8
// speedup vs baseline: 1.1004x; 1.1004x over previous
#include <cuda_runtime.h>
#include <cstdint>

#define N_NODES 100000
#define N_EDGES 1600000
#define SCAN_B 1024
#define NBLK ((N_NODES + SCAN_B - 1) / SCAN_B)

typedef unsigned long long u64;

// ---------------- device scratch (static: no allocations allowed) -------------
__device__ float g_agg[(size_t)N_NODES * 256];
__device__ float g_h1 [(size_t)N_NODES * 256];
__device__ float g_h2 [(size_t)N_NODES * 256];
__device__ float g_deginv[N_NODES];
__device__ int   g_deg[N_NODES];
__device__ int   g_rowptr[N_NODES + 1];
__device__ int   g_cursor[N_NODES];
__device__ int   g_csr[N_EDGES];
__device__ int   g_bsum[NBLK];
__device__ int   g_boff[NBLK];
__device__ int   g_is64;
__device__ float g_s1[256], g_t1[256], g_s2[256], g_t2[256];
__device__ float g_s3[64], g_t3[64], g_t0[64];

// ---------------- packed f32x2 helpers ---------------------------------------
__device__ __forceinline__ u64 pack2(float lo, float hi) {
    u64 r; asm("mov.b64 %0, {%1, %2};" : "=l"(r) : "f"(lo), "f"(hi)); return r;
}
__device__ __forceinline__ void unpack2(u64 v, float& lo, float& hi) {
    asm("mov.b64 {%0, %1}, %2;" : "=f"(lo), "=f"(hi) : "l"(v));
}
__device__ __forceinline__ void ffma2(u64& d, u64 a, u64 b) {
    asm("fma.rn.f32x2 %0, %1, %2, %0;" : "+l"(d) : "l"(a), "l"(b));
}

// ---------------- index dtype detection (int32 vs int64 edge_index) ----------
// If the buffer is int32 node ids read as u64, a word is < N_NODES only when the
// high 32 bits (an independent node id) are 0: P ~ 1e-5 per word, ~0 over 32.
__global__ void detect_kernel(const void* ei) {
    const u64* p = (const u64*)ei;
    int ok = p[threadIdx.x] < (u64)N_NODES;
    unsigned m = __ballot_sync(0xffffffffu, ok);
    if (threadIdx.x == 0) g_is64 = (m == 0xffffffffu);
}

__device__ __forceinline__ int load_idx(const void* p, long long i, int is64) {
    if (is64) return (int)((const long long*)p)[i];
    return ((const int*)p)[i];
}

// ---------------- prep: fold bias+BN into per-channel scale/shift ------------
__global__ void prep_kernel(const float* b1, const float* g1, const float* be1,
                            const float* rm1, const float* rv1,
                            const float* b2, const float* g2, const float* be2,
                            const float* rm2, const float* rv2,
                            const float* bcl) {
    int j = threadIdx.x;
    if (j < 256) {
        float s = g1[j] * rsqrtf(rv1[j] + 1e-5f);
        g_s1[j] = s; g_t1[j] = be1[j] + (b1[j] - rm1[j]) * s;
        s = g2[j] * rsqrtf(rv2[j] + 1e-5f);
        g_s2[j] = s; g_t2[j] = be2[j] + (b2[j] - rm2[j]) * s;
    }
    if (j < 64) { g_s3[j] = 1.0f; g_t3[j] = bcl[j]; g_t0[j] = 0.0f; }
}

// ---------------- CSR build --------------------------------------------------
__global__ void deg_count_kernel(const void* ei) {
    int e = blockIdx.x * blockDim.x + threadIdx.x;
    if (e < N_EDGES) {
        int d = load_idx(ei, (long long)N_EDGES + e, g_is64);
        atomicAdd(&g_deg[d], 1);
    }
}

__global__ void deginv_kernel() {
    int n = blockIdx.x * blockDim.x + threadIdx.x;
    if (n < N_NODES) {
        int d = g_deg[n];
        g_deginv[n] = (d > 0) ? (1.0f / (float)d) : 0.0f;
    }
}

// three-pass exclusive scan of g_deg -> g_rowptr
__global__ void scan1_kernel() {
    __shared__ int sh[SCAN_B];
    int tid = threadIdx.x;
    int idx = blockIdx.x * SCAN_B + tid;
    int v = (idx < N_NODES) ? g_deg[idx] : 0;
    sh[tid] = v;
    __syncthreads();
    #pragma unroll
    for (int off = 1; off < SCAN_B; off <<= 1) {
        int t = (tid >= off) ? sh[tid - off] : 0;
        __syncthreads();
        sh[tid] += t;
        __syncthreads();
    }
    if (idx < N_NODES) g_rowptr[idx] = sh[tid] - v;  // block-local exclusive
    if (tid == SCAN_B - 1) g_bsum[blockIdx.x] = sh[tid];
}

__global__ void scan2_kernel() {  // 1 block, 128 threads, scans NBLK sums
    __shared__ int sh[128];
    int tid = threadIdx.x;
    int v = (tid < NBLK) ? g_bsum[tid] : 0;
    sh[tid] = v;
    __syncthreads();
    #pragma unroll
    for (int off = 1; off < 128; off <<= 1) {
        int t = (tid >= off) ? sh[tid - off] : 0;
        __syncthreads();
        sh[tid] += t;
        __syncthreads();
    }
    if (tid < NBLK) g_boff[tid] = sh[tid] - v;
    if (tid == 127) g_rowptr[N_NODES] = sh[127];
}

__global__ void scan3_kernel() {
    int idx = blockIdx.x * SCAN_B + threadIdx.x;
    if (idx < N_NODES) g_rowptr[idx] += g_boff[blockIdx.x];
}

__global__ void csr_fill_kernel(const void* ei) {
    int e = blockIdx.x * blockDim.x + threadIdx.x;
    if (e < N_EDGES) {
        int is64 = g_is64;
        int s = load_idx(ei, e, is64);
        int d = load_idx(ei, (long long)N_EDGES + e, is64);
        int pos = atomicAdd(&g_cursor[d], 1);
        g_csr[g_rowptr[d] + pos] = s;
    }
}

// ---------------- mean aggregation (gather over CSR) -------------------------
// NPB nodes per 256-thread block; each node served by C/4 threads (float4 lanes)
template <int C, int NPB>
__global__ void agg_mean_kernel(const float4* __restrict__ feat,
                                float4* __restrict__ out) {
    constexpr int CV = C / 4;
    int local = threadIdx.x / CV;
    int ch    = threadIdx.x % CV;
    int n = blockIdx.x * NPB + local;
    if (n >= N_NODES) return;
    int beg = g_rowptr[n], end = g_rowptr[n + 1];
    float4 s0 = make_float4(0.f, 0.f, 0.f, 0.f);
    float4 s1 = make_float4(0.f, 0.f, 0.f, 0.f);
    int i = beg;
    for (; i + 2 <= end; i += 2) {
        int na = g_csr[i], nb = g_csr[i + 1];
        float4 va = feat[(size_t)na * CV + ch];
        float4 vb = feat[(size_t)nb * CV + ch];
        s0.x += va.x; s0.y += va.y; s0.z += va.z; s0.w += va.w;
        s1.x += vb.x; s1.y += vb.y; s1.z += vb.z; s1.w += vb.w;
    }
    if (i < end) {
        int na = g_csr[i];
        float4 va = feat[(size_t)na * CV + ch];
        s0.x += va.x; s0.y += va.y; s0.z += va.z; s0.w += va.w;
    }
    float d = g_deginv[n];
    float4 r;
    r.x = (s0.x + s1.x) * d; r.y = (s0.y + s1.y) * d;
    r.z = (s0.z + s1.z) * d; r.w = (s0.w + s1.w) * d;
    out[(size_t)n * CV + ch] = r;
}

// classifier tail: out[n] = mean-gather(t1)[n] + t2[n]   (C = 64)
template <int NPB>
__global__ void agg_add_out_kernel(const float4* __restrict__ t1,
                                   const float4* __restrict__ t2,
                                   float4* __restrict__ out) {
    constexpr int CV = 16;  // 64 / 4
    int local = threadIdx.x / CV;
    int ch    = threadIdx.x % CV;
    int n = blockIdx.x * NPB + local;
    if (n >= N_NODES) return;
    int beg = g_rowptr[n], end = g_rowptr[n + 1];
    float4 s0 = make_float4(0.f, 0.f, 0.f, 0.f);
    float4 s1 = make_float4(0.f, 0.f, 0.f, 0.f);
    int i = beg;
    for (; i + 2 <= end; i += 2) {
        int na = g_csr[i], nb = g_csr[i + 1];
        float4 va = t1[(size_t)na * CV + ch];
        float4 vb = t1[(size_t)nb * CV + ch];
        s0.x += va.x; s0.y += va.y; s0.z += va.z; s0.w += va.w;
        s1.x += vb.x; s1.y += vb.y; s1.z += vb.z; s1.w += vb.w;
    }
    if (i < end) {
        int na = g_csr[i];
        float4 va = t1[(size_t)na * CV + ch];
        s0.x += va.x; s0.y += va.y; s0.z += va.z; s0.w += va.w;
    }
    float d = g_deginv[n];
    float4 b = t2[(size_t)n * CV + ch];
    float4 r;
    r.x = (s0.x + s1.x) * d + b.x; r.y = (s0.y + s1.y) * d + b.y;
    r.z = (s0.z + s1.z) * d + b.z; r.w = (s0.w + s1.w) * d + b.w;
    out[(size_t)n * CV + ch] = r;
}

// ---------------- fused dual-GEMM: out = relu_bn( A0@B0 + A1@B1 ) -----------
// BK=16, register-prefetch pipeline, packed fma.rn.f32x2 mainloop.
// K2 == 0 -> plain single-matrix GEMM on A0/B0.
template <int K1, int K2, int COUT, int BN, int TN, bool RELU>
__global__ __launch_bounds__(256, 2)
void gemm_fused_kernel(const float* __restrict__ A0, const float* __restrict__ A1,
                       const float* __restrict__ B0, const float* __restrict__ B1,
                       const float* __restrict__ scale, const float* __restrict__ shift,
                       float* __restrict__ out, int Nrows) {
    constexpr int BM = 128, BK = 16, TM = 8;
    __shared__ float As[BK][BM + 4];   // row = 132 floats = 528 B (16B multiple)
    __shared__ float Bs[BK][BN];

    int tid = threadIdx.x;
    int tx = tid & 15, ty = tid >> 4;
    int row0 = blockIdx.x * BM;
    int jb = blockIdx.y * BN;

    u64 acc2[TM / 2][TN];
    #pragma unroll
    for (int i = 0; i < TM / 2; i++)
        #pragma unroll
        for (int j = 0; j < TN; j++) acc2[i][j] = 0ull;

    // A loader: thread -> (row = tid>>1, cols 8*(tid&1) .. +7), two float4
    int rowA = tid >> 1;
    int cA = (tid & 1) * 8;
    int mA = row0 + rowA; if (mA >= Nrows) mA = Nrows - 1;

    // B loader: row = tid>>4 (0..15); BN=128 -> 8 cols/thread, BN=64 -> 4
    int rowB = tid >> 4;
    int cB = (BN == 128) ? (tid & 15) * 8 : (tid & 15) * 4;

    constexpr int KT = (K1 + K2) / BK;

    float4 a0v, a1v, b0v, b1v;
    b1v = make_float4(0.f, 0.f, 0.f, 0.f);

    auto loadA = [&](int kbase, float4& x0, float4& x1) {
        const float* Ap = (kbase < K1) ? A0 + (size_t)mA * K1 + kbase
                                       : A1 + (size_t)mA * K2 + (kbase - K1);
        x0 = *reinterpret_cast<const float4*>(Ap + cA);
        x1 = *reinterpret_cast<const float4*>(Ap + cA + 4);
    };
    auto loadB = [&](int kbase, float4& x0, float4& x1) {
        int kb = kbase + rowB;
        const float* Bp = (kb < K1) ? B0 + (size_t)kb * COUT
                                    : B1 + (size_t)(kb - K1) * COUT;
        x0 = *reinterpret_cast<const float4*>(Bp + jb + cB);
        if (BN == 128) x1 = *reinterpret_cast<const float4*>(Bp + jb + cB + 4);
    };
    auto storeTiles = [&](float4 x0, float4 x1, float4 y0, float4 y1) {
        As[cA + 0][rowA] = x0.x; As[cA + 1][rowA] = x0.y;
        As[cA + 2][rowA] = x0.z; As[cA + 3][rowA] = x0.w;
        As[cA + 4][rowA] = x1.x; As[cA + 5][rowA] = x1.y;
        As[cA + 6][rowA] = x1.z; As[cA + 7][rowA] = x1.w;
        *reinterpret_cast<float4*>(&Bs[rowB][cB]) = y0;
        if (BN == 128) *reinterpret_cast<float4*>(&Bs[rowB][cB + 4]) = y1;
    };

    loadA(0, a0v, a1v); loadB(0, b0v, b1v);
    storeTiles(a0v, a1v, b0v, b1v);
    __syncthreads();

    #pragma unroll 1
    for (int kk = 0; kk < KT; kk++) {
        // prefetch next tile while computing current
        if (kk + 1 < KT) { loadA((kk + 1) * BK, a0v, a1v); loadB((kk + 1) * BK, b0v, b1v); }

        #pragma unroll
        for (int k = 0; k < BK; k++) {
            ulonglong2 aA = *reinterpret_cast<const ulonglong2*>(&As[k][ty * TM]);
            ulonglong2 aB = *reinterpret_cast<const ulonglong2*>(&As[k][ty * TM + 4]);
            u64 ap[TM / 2];
            ap[0] = aA.x; ap[1] = aA.y; ap[2] = aB.x; ap[3] = aB.y;

            float bb[TN];
            float4 q0 = *reinterpret_cast<const float4*>(&Bs[k][tx * TN]);
            bb[0] = q0.x; bb[1] = q0.y; bb[2] = q0.z; bb[3] = q0.w;
            if (TN == 8) {
                float4 q1 = *reinterpret_cast<const float4*>(&Bs[k][tx * TN + 4]);
                bb[4] = q1.x; bb[5] = q1.y; bb[6] = q1.z; bb[7] = q1.w;
            }
            u64 bp[TN];
            #pragma unroll
            for (int j = 0; j < TN; j++) bp[j] = pack2(bb[j], bb[j]);

            #pragma unroll
            for (int i = 0; i < TM / 2; i++)
                #pragma unroll
                for (int j = 0; j < TN; j++)
                    ffma2(acc2[i][j], ap[i], bp[j]);
        }

        __syncthreads();
        if (kk + 1 < KT) {
            storeTiles(a0v, a1v, b0v, b1v);
            __syncthreads();
        }
    }

    float accf[TM][TN];
    #pragma unroll
    for (int i = 0; i < TM / 2; i++)
        #pragma unroll
        for (int j = 0; j < TN; j++)
            unpack2(acc2[i][j], accf[2 * i][j], accf[2 * i + 1][j]);

    float sc[TN], sf[TN];
    #pragma unroll
    for (int j = 0; j < TN; j++) {
        int col = jb + tx * TN + j;
        sc[j] = scale[col];
        sf[j] = shift[col];
    }
    #pragma unroll
    for (int i = 0; i < TM; i++) {
        int m = row0 + ty * TM + i;
        if (m < Nrows) {
            #pragma unroll
            for (int g = 0; g < TN / 4; g++) {
                float4 v;
                v.x = accf[i][g*4+0] * sc[g*4+0] + sf[g*4+0];
                v.y = accf[i][g*4+1] * sc[g*4+1] + sf[g*4+1];
                v.z = accf[i][g*4+2] * sc[g*4+2] + sf[g*4+2];
                v.w = accf[i][g*4+3] * sc[g*4+3] + sf[g*4+3];
                if (RELU) {
                    v.x = fmaxf(v.x, 0.f); v.y = fmaxf(v.y, 0.f);
                    v.z = fmaxf(v.z, 0.f); v.w = fmaxf(v.w, 0.f);
                }
                int col = jb + tx * TN + g * 4;
                *reinterpret_cast<float4*>(&out[(size_t)m * COUT + col]) = v;
            }
        }
    }
}

// ---------------- launch -----------------------------------------------------
extern "C" void kernel_launch(void* const* d_in, const int* in_sizes, int n_in,
                              void* d_out, int out_size) {
    const float* x   = (const float*)d_in[0];
    const void*  ei  = d_in[1];
    const float* W1l = (const float*)d_in[2];
    const float* b1l = (const float*)d_in[3];
    const float* W1r = (const float*)d_in[4];
    const float* g1  = (const float*)d_in[5];
    const float* be1 = (const float*)d_in[6];
    const float* rm1 = (const float*)d_in[7];
    const float* rv1 = (const float*)d_in[8];
    const float* W2l = (const float*)d_in[9];
    const float* b2l = (const float*)d_in[10];
    const float* W2r = (const float*)d_in[11];
    const float* g2  = (const float*)d_in[12];
    const float* be2 = (const float*)d_in[13];
    const float* rm2 = (const float*)d_in[14];
    const float* rv2 = (const float*)d_in[15];
    const float* Wcl = (const float*)d_in[16];
    const float* bcl = (const float*)d_in[17];
    const float* Wcr = (const float*)d_in[18];
    float* out = (float*)d_out;

    void *p_deg, *p_cursor, *p_agg, *p_h1, *p_h2;
    void *p_s1, *p_t1, *p_s2, *p_t2, *p_s3, *p_t3, *p_t0;
    cudaGetSymbolAddress(&p_deg,    g_deg);
    cudaGetSymbolAddress(&p_cursor, g_cursor);
    cudaGetSymbolAddress(&p_agg,    g_agg);
    cudaGetSymbolAddress(&p_h1,     g_h1);
    cudaGetSymbolAddress(&p_h2,     g_h2);
    cudaGetSymbolAddress(&p_s1, g_s1); cudaGetSymbolAddress(&p_t1, g_t1);
    cudaGetSymbolAddress(&p_s2, g_s2); cudaGetSymbolAddress(&p_t2, g_t2);
    cudaGetSymbolAddress(&p_s3, g_s3); cudaGetSymbolAddress(&p_t3, g_t3);
    cudaGetSymbolAddress(&p_t0, g_t0);

    float* agg = (float*)p_agg;
    float* h1  = (float*)p_h1;
    float* h2  = (float*)p_h2;
    float* t1  = agg;                         // [N,64]
    float* t2  = agg + (size_t)N_NODES * 64;  // [N,64]

    cudaMemsetAsync(p_deg,    0, N_NODES * sizeof(int), 0);
    cudaMemsetAsync(p_cursor, 0, N_NODES * sizeof(int), 0);

    detect_kernel<<<1, 32>>>(ei);
    prep_kernel<<<1, 256>>>(b1l, g1, be1, rm1, rv1, b2l, g2, be2, rm2, rv2, bcl);

    int eb = (N_EDGES + 255) / 256;
    deg_count_kernel<<<eb, 256>>>(ei);
    scan1_kernel<<<NBLK, SCAN_B>>>();
    scan2_kernel<<<1, 128>>>();
    scan3_kernel<<<NBLK, SCAN_B>>>();
    deginv_kernel<<<(N_NODES + 255) / 256, 256>>>();
    csr_fill_kernel<<<eb, 256>>>(ei);

    int gx = (N_NODES + 127) / 128;

    // layer 1: mean(x) -> agg [N,128]; h1 = relu(bn(agg@W1l + x@W1r + b1l))
    agg_mean_kernel<128, 8><<<(N_NODES + 7) / 8, 256>>>((const float4*)x, (float4*)agg);
    gemm_fused_kernel<128, 128, 256, 128, 8, true>
        <<<dim3(gx, 2), 256>>>(agg, x, W1l, W1r, (const float*)p_s1, (const float*)p_t1, h1, N_NODES);

    // layer 2
    agg_mean_kernel<256, 4><<<(N_NODES + 3) / 4, 256>>>((const float4*)h1, (float4*)agg);
    gemm_fused_kernel<256, 256, 256, 128, 8, true>
        <<<dim3(gx, 2), 256>>>(agg, h1, W2l, W2r, (const float*)p_s2, (const float*)p_t2, h2, N_NODES);

    // classifier, linearity-reordered: t1 = h2@Wcl ; t2 = h2@Wcr + bcl ;
    // out = mean-gather(t1) + t2   (aggregates 64 channels instead of 256)
    gemm_fused_kernel<256, 0, 64, 64, 4, false>
        <<<dim3(gx, 1), 256>>>(h2, h2, Wcl, Wcl, (const float*)p_s3, (const float*)p_t0, t1, N_NODES);
    gemm_fused_kernel<256, 0, 64, 64, 4, false>
        <<<dim3(gx, 1), 256>>>(h2, h2, Wcr, Wcr, (const float*)p_s3, (const float*)p_t3, t2, N_NODES);
    agg_add_out_kernel<16><<<(N_NODES + 15) / 16, 256>>>(
        (const float4*)t1, (const float4*)t2, (float4*)out);
}